// round 1
// baseline (speedup 1.0000x reference)
#include <cuda_runtime.h>
#include <cuda_bf16.h>
#include <cstdint>
#include <math_constants.h>

#define BATCH 32
#define SLEN  2048
#define DDIM  128
#define HDIM  256
#define KCODE 512

// ---------------- scratch (static device globals; no allocation) ----------------
__device__ float g_h1[(size_t)BATCH * HDIM * SLEN];   // 64 MB
__device__ float g_h2[(size_t)BATCH * HDIM * SLEN];   // 64 MB
__device__ float g_z [(size_t)BATCH * DDIM * SLEN];   // 32 MB
__device__ float g_zq[(size_t)BATCH * DDIM * SLEN];   // 32 MB
__device__ float g_c2[KCODE];
__device__ double g_acc[2];                            // [0]=sum min dist, [1]=recon SSE

// ---------------- init ----------------
__global__ void init_k() {
    if (threadIdx.x < 2) g_acc[threadIdx.x] = 0.0;
}

// ---------------- codebook norms ----------------
__global__ void c2_k(const float* __restrict__ cb) {
    int k = blockIdx.x * blockDim.x + threadIdx.x;
    if (k < KCODE) {
        const float* r = cb + (size_t)k * DDIM;
        float s = 0.f;
        #pragma unroll 8
        for (int d = 0; d < DDIM; d++) s += r[d] * r[d];
        g_c2[k] = s;
    }
}

// ---------------- encoder conv1: 1 -> H, k=3, SAME, lrelu ----------------
__global__ __launch_bounds__(256) void enc1_k(const float* __restrict__ x,
                                              const float* __restrict__ w,
                                              const float* __restrict__ bias) {
    size_t idx = (size_t)blockIdx.x * blockDim.x + threadIdx.x;   // over B*H*S
    int s = idx & (SLEN - 1);
    int c = (idx >> 11) & (HDIM - 1);
    int b = idx >> 19;
    const float* xb = x + (size_t)b * SLEN;
    float v = bias[c];
    float w0 = w[c*3+0], w1 = w[c*3+1], w2 = w[c*3+2];
    if (s > 0)        v += w0 * xb[s-1];
    v += w1 * xb[s];
    if (s < SLEN - 1) v += w2 * xb[s+1];
    g_h1[idx] = (v >= 0.f) ? v : 0.2f * v;
}

// ---------------- generic conv: CI -> CO, k=3, SAME (implicit GEMM tile) ------
// tile: 128 co x 64 s per 256-thread block; ci chunked by 16.
template<int CI, int CO, bool RELU>
__global__ __launch_bounds__(256) void conv_k(const float* __restrict__ in,
                                              const float* __restrict__ w,
                                              const float* __restrict__ bias,
                                              float* __restrict__ out) {
    const int s_tile  = blockIdx.x * 64;
    const int co_base = blockIdx.y * 128;
    const int b       = blockIdx.z;
    const int tid = threadIdx.x;
    const int tx  = tid & 15;    // s group   (4 outputs)
    const int ty  = tid >> 4;    // co group  (8 outputs)

    __shared__ float ws[48 * 130];       // [ci*3+t][co], stride 130
    __shared__ float ins[16][72];        // [ci][sp], sp in 0..65

    float acc[8][4];
    #pragma unroll
    for (int v = 0; v < 8; v++)
        #pragma unroll
        for (int u = 0; u < 4; u++) acc[v][u] = 0.f;

    const float* in_b = in + (size_t)b * CI * SLEN;

    for (int ci0 = 0; ci0 < CI; ci0 += 16) {
        __syncthreads();
        // load input chunk: 16 ci x 66 s (with halo, zero-padded)
        for (int i = tid; i < 16 * 66; i += 256) {
            int ci = i / 66, sp = i - ci * 66;
            int s = s_tile - 1 + sp;
            float v = 0.f;
            if (s >= 0 && s < SLEN) v = in_b[(size_t)(ci0 + ci) * SLEN + s];
            ins[ci][sp] = v;
        }
        // load weight chunk: 128 co x 16 ci x 3 t (coalesced along (ci,t))
        for (int i = tid; i < 128 * 48; i += 256) {
            int co = i / 48, j = i - co * 48;            // j = ci_local*3 + t
            ws[j * 130 + co] = w[(size_t)(co_base + co) * (CI * 3) + (size_t)ci0 * 3 + j];
        }
        __syncthreads();

        #pragma unroll
        for (int ci = 0; ci < 16; ci++) {
            float xv[6];
            #pragma unroll
            for (int u = 0; u < 6; u++) xv[u] = ins[ci][tx * 4 + u];
            #pragma unroll
            for (int t = 0; t < 3; t++) {
                float wv[8];
                #pragma unroll
                for (int v = 0; v < 8; v++) wv[v] = ws[(ci * 3 + t) * 130 + ty * 8 + v];
                #pragma unroll
                for (int v = 0; v < 8; v++)
                    #pragma unroll
                    for (int u = 0; u < 4; u++)
                        acc[v][u] += wv[v] * xv[u + t];
            }
        }
    }

    #pragma unroll
    for (int v = 0; v < 8; v++) {
        int co = co_base + ty * 8 + v;
        float bb = bias[co];
        #pragma unroll
        for (int u = 0; u < 4; u++) {
            int s = s_tile + tx * 4 + u;
            float r = acc[v][u] + bb;
            if (RELU) r = (r >= 0.f) ? r : 0.2f * r;
            out[((size_t)b * CO + co) * SLEN + s] = r;
        }
    }
}

// ---------------- VQ: nearest code, gather z_q, loss accumulation ------------
__global__ __launch_bounds__(256) void vq_k(const float* __restrict__ cb,
                                            float* __restrict__ out_idx) {
    int gp = blockIdx.x * 256 + threadIdx.x;     // global position in [0, B*S)
    int b = gp >> 11;
    int s = gp & (SLEN - 1);

    const float* zb = g_z + (size_t)b * DDIM * SLEN + s;
    float zr[DDIM];
    #pragma unroll
    for (int d = 0; d < DDIM; d++) zr[d] = zb[(size_t)d * SLEN];

    float z2 = 0.f;
    #pragma unroll
    for (int d = 0; d < DDIM; d++) z2 += zr[d] * zr[d];

    float best = CUDART_INF_F;
    int bi = 0;
    const float4* cb4 = reinterpret_cast<const float4*>(cb);
    for (int k = 0; k < KCODE; k++) {
        float d0 = 0.f, d1 = 0.f, d2 = 0.f, d3 = 0.f;
        #pragma unroll
        for (int q = 0; q < 32; q++) {
            float4 c = __ldg(&cb4[k * 32 + q]);
            d0 += c.x * zr[4*q+0];
            d1 += c.y * zr[4*q+1];
            d2 += c.z * zr[4*q+2];
            d3 += c.w * zr[4*q+3];
        }
        float dist = z2 + __ldg(&g_c2[k]) - 2.f * ((d0 + d1) + (d2 + d3));
        if (dist < best) { best = dist; bi = k; }
    }

    out_idx[gp] = (float)bi;

    // gather z_q and compute exact ||z - c||^2 (matches reference loss)
    const float* cc = cb + (size_t)bi * DDIM;
    float* zqb = g_zq + (size_t)b * DDIM * SLEN + s;
    float qs = 0.f;
    #pragma unroll
    for (int d = 0; d < DDIM; d++) {
        float c = cc[d];
        zqb[(size_t)d * SLEN] = c;
        float df = zr[d] - c;
        qs += df * df;
    }

    // block reduce qs -> atomicAdd
    __shared__ float red[256];
    red[threadIdx.x] = qs;
    __syncthreads();
    for (int off = 128; off > 0; off >>= 1) {
        if (threadIdx.x < off) red[threadIdx.x] += red[threadIdx.x + off];
        __syncthreads();
    }
    if (threadIdx.x == 0) atomicAdd(&g_acc[0], (double)red[0]);
}

// ---------------- decoder conv3: H -> 1, k=3 + recon loss --------------------
__global__ __launch_bounds__(256) void dec3_k(const float* __restrict__ w,
                                              const float* __restrict__ bias,
                                              const float* __restrict__ x,
                                              float* __restrict__ xrec) {
    __shared__ float ws[HDIM * 3];
    for (int i = threadIdx.x; i < HDIM * 3; i += 256) ws[i] = w[i];
    __syncthreads();

    int b = blockIdx.y;
    int s = blockIdx.x * 256 + threadIdx.x;
    const float* hb = g_h2 + (size_t)b * HDIM * SLEN;

    float a = bias[0];
    bool lok = (s > 0), rok = (s < SLEN - 1);
    #pragma unroll 4
    for (int ci = 0; ci < HDIM; ci++) {
        const float* r = hb + (size_t)ci * SLEN + s;
        float w0 = ws[ci*3], w1 = ws[ci*3+1], w2 = ws[ci*3+2];
        if (lok) a += w0 * r[-1];
        a += w1 * r[0];
        if (rok) a += w2 * r[1];
    }
    xrec[(size_t)b * SLEN + s] = a;

    float diff = x[(size_t)b * SLEN + s] - a;
    float sq = diff * diff;

    __shared__ float red[256];
    red[threadIdx.x] = sq;
    __syncthreads();
    for (int off = 128; off > 0; off >>= 1) {
        if (threadIdx.x < off) red[threadIdx.x] += red[threadIdx.x + off];
        __syncthreads();
    }
    if (threadIdx.x == 0) atomicAdd(&g_acc[1], (double)red[0]);
}

// ---------------- finalize losses ----------------
__global__ void fin_k(float* __restrict__ out) {
    double qsum = g_acc[0];
    double rsum = g_acc[1];
    float qm    = (float)(qsum / ((double)BATCH * SLEN * DDIM));
    float recon = (float)(rsum / ((double)BATCH * SLEN));
    float vq    = qm * 0.05f;
    float com   = qm * 0.15f;
    size_t base = (size_t)2 * BATCH * SLEN;   // after x_recon and indices
    out[base + 0] = recon + vq + com;
    out[base + 1] = recon;
    out[base + 2] = vq;
    out[base + 3] = com;
}

// ---------------- launch ----------------
extern "C" void kernel_launch(void* const* d_in, const int* in_sizes, int n_in,
                              void* d_out, int out_size) {
    const float* x   = (const float*)d_in[0];
    const float* cb  = (const float*)d_in[1];
    const float* ew1 = (const float*)d_in[2];
    const float* eb1 = (const float*)d_in[3];
    const float* ew2 = (const float*)d_in[4];
    const float* eb2 = (const float*)d_in[5];
    const float* ew3 = (const float*)d_in[6];
    const float* eb3 = (const float*)d_in[7];
    const float* dw1 = (const float*)d_in[8];
    const float* db1 = (const float*)d_in[9];
    const float* dw2 = (const float*)d_in[10];
    const float* db2 = (const float*)d_in[11];
    const float* dw3 = (const float*)d_in[12];
    const float* db3 = (const float*)d_in[13];
    float* out = (float*)d_out;

    float* h1_ptr; cudaGetSymbolAddress((void**)&h1_ptr, g_h1);
    float* h2_ptr; cudaGetSymbolAddress((void**)&h2_ptr, g_h2);
    float* z_ptr;  cudaGetSymbolAddress((void**)&z_ptr,  g_z);
    float* zq_ptr; cudaGetSymbolAddress((void**)&zq_ptr, g_zq);

    init_k<<<1, 32>>>();
    c2_k<<<2, 256>>>(cb);

    // encoder
    enc1_k<<<(BATCH * HDIM * SLEN) / 256, 256>>>(x, ew1, eb1);

    dim3 g2(SLEN / 64, HDIM / 128, BATCH);
    conv_k<HDIM, HDIM, true><<<g2, 256>>>(h1_ptr, ew2, eb2, h2_ptr);

    dim3 g3(SLEN / 64, DDIM / 128, BATCH);
    conv_k<HDIM, DDIM, false><<<g3, 256>>>(h2_ptr, ew3, eb3, z_ptr);

    // VQ (writes indices region of d_out)
    vq_k<<<(BATCH * SLEN) / 256, 256>>>(cb, out + (size_t)BATCH * SLEN);

    // decoder
    dim3 g4(SLEN / 64, HDIM / 128, BATCH);
    conv_k<DDIM, HDIM, true><<<g4, 256>>>(zq_ptr, dw1, db1, h1_ptr);

    dim3 g5(SLEN / 64, HDIM / 128, BATCH);
    conv_k<HDIM, HDIM, true><<<g5, 256>>>(h1_ptr, dw2, db2, h2_ptr);

    dim3 g6(SLEN / 256, BATCH);
    dec3_k<<<g6, 256>>>(dw3, db3, x, out);

    fin_k<<<1, 1>>>(out);
}

// round 5
// speedup vs baseline: 1.1359x; 1.1359x over previous
#include <cuda_runtime.h>
#include <cuda_bf16.h>
#include <cstdint>
#include <math_constants.h>

#define BATCH 32
#define SLEN  2048
#define DDIM  128
#define HDIM  256
#define KCODE 512

// ---------------- scratch (static device globals; no allocation) ----------------
// g_h1/g_h2: channel-FIRST [b][c][s] for encoder; reused channel-LAST [p][c] by decoder.
// g_z: channel-first [b][d][s].  g_zq: channel-LAST [p][d] (feeds MMA decoder).
__device__ float g_h1[(size_t)BATCH * HDIM * SLEN];   // 64 MB
__device__ float g_h2[(size_t)BATCH * HDIM * SLEN];   // 64 MB
__device__ float g_z [(size_t)BATCH * DDIM * SLEN];   // 32 MB
__device__ float g_zq[(size_t)BATCH * SLEN * DDIM];   // 32 MB (channel-last)
__device__ float g_wh[HDIM * 3 * HDIM];               // K-major weight hi (tf32)
__device__ float g_wl[HDIM * 3 * HDIM];               // K-major weight lo (tf32)
__device__ float g_c2[KCODE];
__device__ double g_acc[2];                            // [0]=sum min dist, [1]=recon SSE

// ---------------- helpers ----------------
__device__ __forceinline__ float tf32_rna(float v) {
    uint32_t o;
    asm("cvt.rna.tf32.f32 %0, %1;" : "=r"(o) : "f"(v));
    return __uint_as_float(o);
}

__device__ __forceinline__ void mma1688_tf32(float* d, const float* a, const float* b) {
    asm volatile(
        "mma.sync.aligned.m16n8k8.row.col.f32.tf32.tf32.f32 "
        "{%0,%1,%2,%3}, {%4,%5,%6,%7}, {%8,%9}, {%0,%1,%2,%3};"
        : "+f"(d[0]), "+f"(d[1]), "+f"(d[2]), "+f"(d[3])
        : "r"(__float_as_uint(a[0])), "r"(__float_as_uint(a[1])),
          "r"(__float_as_uint(a[2])), "r"(__float_as_uint(a[3])),
          "r"(__float_as_uint(b[0])), "r"(__float_as_uint(b[1])));
}

// ---------------- init ----------------
__global__ void init_k() {
    if (threadIdx.x < 2) g_acc[threadIdx.x] = 0.0;
}

// ---------------- codebook norms ----------------
__global__ void c2_k(const float* __restrict__ cb) {
    int k = blockIdx.x * blockDim.x + threadIdx.x;
    if (k < KCODE) {
        const float* r = cb + (size_t)k * DDIM;
        float s = 0.f;
        #pragma unroll 8
        for (int d = 0; d < DDIM; d++) s += r[d] * r[d];
        g_c2[k] = s;
    }
}

// ---------------- encoder conv1: 1 -> H, k=3, SAME, lrelu (round-1 proven) ---
__global__ __launch_bounds__(256) void enc1_k(const float* __restrict__ x,
                                              const float* __restrict__ w,
                                              const float* __restrict__ bias) {
    size_t idx = (size_t)blockIdx.x * blockDim.x + threadIdx.x;   // over B*H*S
    int s = idx & (SLEN - 1);
    int c = (idx >> 11) & (HDIM - 1);
    int b = idx >> 19;
    const float* xb = x + (size_t)b * SLEN;
    float v = bias[c];
    float w0 = w[c*3+0], w1 = w[c*3+1], w2 = w[c*3+2];
    if (s > 0)        v += w0 * xb[s-1];
    v += w1 * xb[s];
    if (s < SLEN - 1) v += w2 * xb[s+1];
    g_h1[idx] = (v >= 0.f) ? v : 0.2f * v;
}

// ------------ SIMT fp32 conv (round-1 proven): channel-first ------------
template<int CI, int CO, bool RELU>
__global__ __launch_bounds__(256) void conv_k(const float* __restrict__ in,
                                              const float* __restrict__ w,
                                              const float* __restrict__ bias,
                                              float* __restrict__ out) {
    const int s_tile  = blockIdx.x * 64;
    const int co_base = blockIdx.y * 128;
    const int b       = blockIdx.z;
    const int tid = threadIdx.x;
    const int tx  = tid & 15;    // s group   (4 outputs)
    const int ty  = tid >> 4;    // co group  (8 outputs)

    __shared__ float ws[48 * 130];       // [ci*3+t][co], stride 130
    __shared__ float ins[16][72];        // [ci][sp], sp in 0..65

    float acc[8][4];
    #pragma unroll
    for (int v = 0; v < 8; v++)
        #pragma unroll
        for (int u = 0; u < 4; u++) acc[v][u] = 0.f;

    const float* in_b = in + (size_t)b * CI * SLEN;

    for (int ci0 = 0; ci0 < CI; ci0 += 16) {
        __syncthreads();
        for (int i = tid; i < 16 * 66; i += 256) {
            int ci = i / 66, sp = i - ci * 66;
            int s = s_tile - 1 + sp;
            float v = 0.f;
            if (s >= 0 && s < SLEN) v = in_b[(size_t)(ci0 + ci) * SLEN + s];
            ins[ci][sp] = v;
        }
        for (int i = tid; i < 128 * 48; i += 256) {
            int co = i / 48, j = i - co * 48;            // j = ci_local*3 + t
            ws[j * 130 + co] = w[(size_t)(co_base + co) * (CI * 3) + (size_t)ci0 * 3 + j];
        }
        __syncthreads();

        #pragma unroll
        for (int ci = 0; ci < 16; ci++) {
            float xv[6];
            #pragma unroll
            for (int u = 0; u < 6; u++) xv[u] = ins[ci][tx * 4 + u];
            #pragma unroll
            for (int t = 0; t < 3; t++) {
                float wv[8];
                #pragma unroll
                for (int v = 0; v < 8; v++) wv[v] = ws[(ci * 3 + t) * 130 + ty * 8 + v];
                #pragma unroll
                for (int v = 0; v < 8; v++)
                    #pragma unroll
                    for (int u = 0; u < 4; u++)
                        acc[v][u] += wv[v] * xv[u + t];
            }
        }
    }

    #pragma unroll
    for (int v = 0; v < 8; v++) {
        int co = co_base + ty * 8 + v;
        float bb = bias[co];
        #pragma unroll
        for (int u = 0; u < 4; u++) {
            int s = s_tile + tx * 4 + u;
            float r = acc[v][u] + bb;
            if (RELU) r = (r >= 0.f) ? r : 0.2f * r;
            out[((size_t)b * CO + co) * SLEN + s] = r;
        }
    }
}

// ---------------- VQ (round-1 proven, channel-first z), z_q stored channel-last
__global__ __launch_bounds__(256) void vq_k(const float* __restrict__ cb,
                                            float* __restrict__ out_idx) {
    int gp = blockIdx.x * 256 + threadIdx.x;     // global position in [0, B*S)
    int b = gp >> 11;
    int s = gp & (SLEN - 1);

    const float* zb = g_z + (size_t)b * DDIM * SLEN + s;
    float zr[DDIM];
    #pragma unroll
    for (int d = 0; d < DDIM; d++) zr[d] = zb[(size_t)d * SLEN];

    float z2 = 0.f;
    #pragma unroll
    for (int d = 0; d < DDIM; d++) z2 += zr[d] * zr[d];

    float best = CUDART_INF_F;
    int bi = 0;
    const float4* cb4 = reinterpret_cast<const float4*>(cb);
    for (int k = 0; k < KCODE; k++) {
        float d0 = 0.f, d1 = 0.f, d2 = 0.f, d3 = 0.f;
        #pragma unroll
        for (int q = 0; q < 32; q++) {
            float4 c = __ldg(&cb4[k * 32 + q]);
            d0 += c.x * zr[4*q+0];
            d1 += c.y * zr[4*q+1];
            d2 += c.z * zr[4*q+2];
            d3 += c.w * zr[4*q+3];
        }
        float dist = z2 + __ldg(&g_c2[k]) - 2.f * ((d0 + d1) + (d2 + d3));
        if (dist < best) { best = dist; bi = k; }
    }

    out_idx[gp] = (float)bi;

    // gather z_q (channel-last, coalesced) and exact ||z - c||^2 (round-1 order)
    const float* cc = cb + (size_t)bi * DDIM;
    float4* zq = reinterpret_cast<float4*>(g_zq + (size_t)gp * DDIM);
    float qs = 0.f;
    #pragma unroll
    for (int d = 0; d < DDIM; d++) {
        float df = zr[d] - cc[d];
        qs += df * df;
    }
    #pragma unroll
    for (int q = 0; q < 32; q++) zq[q] = __ldg(reinterpret_cast<const float4*>(cc) + q);

    __shared__ float red[256];
    red[threadIdx.x] = qs;
    __syncthreads();
    for (int off = 128; off > 0; off >>= 1) {
        if (threadIdx.x < off) red[threadIdx.x] += red[threadIdx.x + off];
        __syncthreads();
    }
    if (threadIdx.x == 0) atomicAdd(&g_acc[0], (double)red[0]);
}

// weight prep: [CO][ci*3+t] fp32 -> K-major [CO][t*CI+ci] tf32 hi/lo
template<int CO, int CI>
__global__ __launch_bounds__(256) void wprep_k(const float* __restrict__ w,
                                               float* __restrict__ wh,
                                               float* __restrict__ wl) {
    int idx = blockIdx.x * 256 + threadIdx.x;        // over CO*3*CI
    int co = idx / (3 * CI);
    int r  = idx - co * (3 * CI);                    // = t*CI + ci
    int t  = r / CI;
    int ci = r - t * CI;
    float v = w[(size_t)co * 3 * CI + (size_t)ci * 3 + t];
    float h = tf32_rna(v);
    wh[idx] = h;
    wl[idx] = tf32_rna(v - h);
}

// ============ 3xTF32 HMMA conv: CI -> CO, k=3 SAME, channel-last ============
template<int CI, int CO, bool RELU>
__global__ __launch_bounds__(256, 2) void conv_mma_k(const float* __restrict__ in,
                                                     const float* __restrict__ wh,
                                                     const float* __restrict__ wl,
                                                     const float* __restrict__ bias,
                                                     float* __restrict__ out) {
    constexpr int KTOT = 3 * CI;
    constexpr int NCH  = KTOT / 32;
    constexpr int RSTR = 36;                 // floats per smem row (32 + 4 pad)

    extern __shared__ float sm[];
    float* Ah = sm;
    float* Al = sm + 128 * RSTR;
    float* Bh = sm + 2 * 128 * RSTR;
    float* Bl = sm + 3 * 128 * RSTR;

    const int tid  = threadIdx.x;
    const int lane = tid & 31;
    const int wid  = tid >> 5;
    const int wm   = wid & 1;                // 2 warps over co
    const int wn   = wid >> 1;               // 4 warps over p
    const int g    = lane >> 2;              // group id 0..7
    const int t4   = lane & 3;               // thread-in-group 0..3

    const int bs_base = blockIdx.x * 128;
    const int co_base = blockIdx.y * 128;
    const int s_in_b0 = bs_base & (SLEN - 1);

    float acc[4][4][4];
    #pragma unroll
    for (int i = 0; i < 4; i++)
        #pragma unroll
        for (int j = 0; j < 4; j++)
            #pragma unroll
            for (int e = 0; e < 4; e++) acc[i][j][e] = 0.f;

    for (int kc = 0; kc < NCH; kc++) {
        const int t   = (kc * 32) / CI;       // tap (chunk never crosses taps; CI%32==0)
        const int ci0 = (kc * 32) % CI;
        __syncthreads();

        #pragma unroll
        for (int j = 0; j < 4; j++) {
            int idx = tid + 256 * j;          // 1024 float4
            int row = idx >> 3, q = idx & 7;
            size_t src = (size_t)(co_base + row) * KTOT + kc * 32 + 4 * q;
            float4 vh = *reinterpret_cast<const float4*>(wh + src);
            float4 vl = *reinterpret_cast<const float4*>(wl + src);
            *reinterpret_cast<float4*>(Ah + row * RSTR + 4 * q) = vh;
            *reinterpret_cast<float4*>(Al + row * RSTR + 4 * q) = vl;
        }
        #pragma unroll
        for (int j = 0; j < 4; j++) {
            int idx = tid + 256 * j;          // 1024 float4
            int row = idx >> 3, q = idx & 7;
            int sb = s_in_b0 + row + t - 1;
            float4 v = make_float4(0.f, 0.f, 0.f, 0.f);
            if (sb >= 0 && sb < SLEN)
                v = *reinterpret_cast<const float4*>(
                        in + (size_t)(bs_base + row + t - 1) * CI + ci0 + 4 * q);
            float4 h, l;
            h.x = tf32_rna(v.x); l.x = tf32_rna(v.x - h.x);
            h.y = tf32_rna(v.y); l.y = tf32_rna(v.y - h.y);
            h.z = tf32_rna(v.z); l.z = tf32_rna(v.z - h.z);
            h.w = tf32_rna(v.w); l.w = tf32_rna(v.w - h.w);
            *reinterpret_cast<float4*>(Bh + row * RSTR + 4 * q) = h;
            *reinterpret_cast<float4*>(Bl + row * RSTR + 4 * q) = l;
        }
        __syncthreads();

        #pragma unroll
        for (int ks = 0; ks < 4; ks++) {
            const int k0 = ks * 8 + t4;       // this thread's k column
            float bh[4][2], bl[4][2];
            #pragma unroll
            for (int nf = 0; nf < 4; nf++) {
                int nrow = wn * 32 + nf * 8 + g;
                bh[nf][0] = Bh[nrow * RSTR + k0];
                bh[nf][1] = Bh[nrow * RSTR + k0 + 4];
                bl[nf][0] = Bl[nrow * RSTR + k0];
                bl[nf][1] = Bl[nrow * RSTR + k0 + 4];
            }
            #pragma unroll
            for (int mf = 0; mf < 4; mf++) {
                int mrow = wm * 64 + mf * 16 + g;
                float ah[4], al[4];
                ah[0] = Ah[mrow * RSTR + k0];
                ah[1] = Ah[(mrow + 8) * RSTR + k0];
                ah[2] = Ah[mrow * RSTR + k0 + 4];
                ah[3] = Ah[(mrow + 8) * RSTR + k0 + 4];
                al[0] = Al[mrow * RSTR + k0];
                al[1] = Al[(mrow + 8) * RSTR + k0];
                al[2] = Al[mrow * RSTR + k0 + 4];
                al[3] = Al[(mrow + 8) * RSTR + k0 + 4];
                #pragma unroll
                for (int nf = 0; nf < 4; nf++) {
                    mma1688_tf32(acc[mf][nf], ah, bh[nf]);
                    mma1688_tf32(acc[mf][nf], ah, bl[nf]);
                    mma1688_tf32(acc[mf][nf], al, bh[nf]);
                }
            }
        }
    }

    #pragma unroll
    for (int mf = 0; mf < 4; mf++) {
        int co0 = co_base + wm * 64 + mf * 16 + g;
        float bb0 = bias[co0];
        float bb1 = bias[co0 + 8];
        #pragma unroll
        for (int nf = 0; nf < 4; nf++) {
            int p = bs_base + wn * 32 + nf * 8 + t4 * 2;
            #pragma unroll
            for (int e = 0; e < 2; e++) {
                float v0 = acc[mf][nf][e] + bb0;       // row g,   col t4*2+e
                float v1 = acc[mf][nf][2 + e] + bb1;   // row g+8, col t4*2+e
                if (RELU) {
                    v0 = (v0 >= 0.f) ? v0 : 0.2f * v0;
                    v1 = (v1 >= 0.f) ? v1 : 0.2f * v1;
                }
                out[(size_t)(p + e) * CO + co0]     = v0;
                out[(size_t)(p + e) * CO + co0 + 8] = v1;
            }
        }
    }
}

// ---------------- decoder conv3: H -> 1 (channel-last input) + recon loss ----
__global__ __launch_bounds__(256) void dec3_k(const float* __restrict__ w,
                                              const float* __restrict__ bias,
                                              const float* __restrict__ x,
                                              float* __restrict__ xrec) {
    __shared__ float ws[HDIM * 3];
    for (int i = threadIdx.x; i < HDIM * 3; i += 256) ws[i] = w[i];
    __syncthreads();

    int wid = threadIdx.x >> 5, lane = threadIdx.x & 31;
    int p = blockIdx.x * 8 + wid;     // global position
    int s = p & (SLEN - 1);

    float acc = 0.f;
    #pragma unroll
    for (int t = 0; t < 3; t++) {
        int sb = s + t - 1;
        if (sb < 0 || sb >= SLEN) continue;
        const float4* r = reinterpret_cast<const float4*>(g_h2 + (size_t)(p + t - 1) * HDIM);
        #pragma unroll
        for (int q = 0; q < 2; q++) {
            float4 v = r[lane * 2 + q];
            int c0 = lane * 8 + q * 4;
            acc += v.x * ws[(c0+0)*3+t] + v.y * ws[(c0+1)*3+t]
                 + v.z * ws[(c0+2)*3+t] + v.w * ws[(c0+3)*3+t];
        }
    }
    #pragma unroll
    for (int off = 16; off > 0; off >>= 1)
        acc += __shfl_xor_sync(0xFFFFFFFFu, acc, off);

    __shared__ float wsum[8];
    if (lane == 0) {
        float a = acc + bias[0];
        xrec[p] = a;
        float diff = x[p] - a;
        wsum[wid] = diff * diff;
    }
    __syncthreads();
    if (threadIdx.x == 0) {
        float s8 = 0.f;
        #pragma unroll
        for (int i = 0; i < 8; i++) s8 += wsum[i];
        atomicAdd(&g_acc[1], (double)s8);
    }
}

// ---------------- finalize losses ----------------
__global__ void fin_k(float* __restrict__ out) {
    double qsum = g_acc[0];
    double rsum = g_acc[1];
    float qm    = (float)(qsum / ((double)BATCH * SLEN * DDIM));
    float recon = (float)(rsum / ((double)BATCH * SLEN));
    float vq    = qm * 0.05f;
    float com   = qm * 0.15f;
    size_t base = (size_t)2 * BATCH * SLEN;
    out[base + 0] = recon + vq + com;
    out[base + 1] = recon;
    out[base + 2] = vq;
    out[base + 3] = com;
}

// ---------------- launch ----------------
static const int CONV_SMEM = 4 * 128 * 36 * 4;   // 73728 bytes

extern "C" void kernel_launch(void* const* d_in, const int* in_sizes, int n_in,
                              void* d_out, int out_size) {
    const float* x   = (const float*)d_in[0];
    const float* cb  = (const float*)d_in[1];
    const float* ew1 = (const float*)d_in[2];
    const float* eb1 = (const float*)d_in[3];
    const float* ew2 = (const float*)d_in[4];
    const float* eb2 = (const float*)d_in[5];
    const float* ew3 = (const float*)d_in[6];
    const float* eb3 = (const float*)d_in[7];
    const float* dw1 = (const float*)d_in[8];
    const float* db1 = (const float*)d_in[9];
    const float* dw2 = (const float*)d_in[10];
    const float* db2 = (const float*)d_in[11];
    const float* dw3 = (const float*)d_in[12];
    const float* db3 = (const float*)d_in[13];
    float* out = (float*)d_out;

    float* h1_ptr; cudaGetSymbolAddress((void**)&h1_ptr, g_h1);
    float* h2_ptr; cudaGetSymbolAddress((void**)&h2_ptr, g_h2);
    float* z_ptr;  cudaGetSymbolAddress((void**)&z_ptr,  g_z);
    float* zq_ptr; cudaGetSymbolAddress((void**)&zq_ptr, g_zq);
    float* wh_ptr; cudaGetSymbolAddress((void**)&wh_ptr, g_wh);
    float* wl_ptr; cudaGetSymbolAddress((void**)&wl_ptr, g_wl);

    cudaFuncSetAttribute(conv_mma_k<DDIM, HDIM, true>,
                         cudaFuncAttributeMaxDynamicSharedMemorySize, CONV_SMEM);
    cudaFuncSetAttribute(conv_mma_k<HDIM, HDIM, true>,
                         cudaFuncAttributeMaxDynamicSharedMemorySize, CONV_SMEM);

    init_k<<<1, 32>>>();
    c2_k<<<2, 256>>>(cb);

    // ---------- encoder: round-1 proven fp32 path (channel-first) ----------
    enc1_k<<<(BATCH * HDIM * SLEN) / 256, 256>>>(x, ew1, eb1);

    dim3 g2(SLEN / 64, HDIM / 128, BATCH);
    conv_k<HDIM, HDIM, true><<<g2, 256>>>(h1_ptr, ew2, eb2, h2_ptr);

    dim3 g3(SLEN / 64, DDIM / 128, BATCH);
    conv_k<HDIM, DDIM, false><<<g3, 256>>>(h2_ptr, ew3, eb3, z_ptr);

    // ---------- VQ: round-1 proven; z_q written channel-last ----------
    vq_k<<<(BATCH * SLEN) / 256, 256>>>(cb, out + (size_t)BATCH * SLEN);

    // ---------- decoder: 3xTF32 MMA (channel-last) ----------
    const int STILES = (BATCH * SLEN) / 128;   // 512

    wprep_k<HDIM, DDIM><<<(HDIM * 3 * DDIM) / 256, 256>>>(dw1, wh_ptr, wl_ptr);
    conv_mma_k<DDIM, HDIM, true><<<dim3(STILES, HDIM / 128), 256, CONV_SMEM>>>(
        zq_ptr, wh_ptr, wl_ptr, db1, h1_ptr);

    wprep_k<HDIM, HDIM><<<(HDIM * 3 * HDIM) / 256, 256>>>(dw2, wh_ptr, wl_ptr);
    conv_mma_k<HDIM, HDIM, true><<<dim3(STILES, HDIM / 128), 256, CONV_SMEM>>>(
        h1_ptr, wh_ptr, wl_ptr, db2, h2_ptr);

    dec3_k<<<(BATCH * SLEN) / 8, 256>>>(dw3, db3, x, out);

    fin_k<<<1, 1>>>(out);
}